// round 2
// baseline (speedup 1.0000x reference)
#include <cuda_runtime.h>
#include <cuda_bf16.h>

// TripletLoss on GB300:
//   loss = mean_t softplus( d(i,j) - d(i,k) ),  d(a,b)=max(|xa|^2+|xb|^2-2 xa.xb, 0)
// features: [8192,128] fp32. triplets: [1M,3] — dtype may be int32 (JAX x64
// disabled aliases jnp.int64->int32) or genuine int64; detected at runtime.
//
// Warp-per-triplet, float4 coalesced row loads (features = 4MB, L2-resident),
// 2 triplets/warp/iter for MLP, joint butterfly shfl reduction, double-atomic
// block partials. Expected: L2-bandwidth bound (~1.5GB row reads).

#define MAX_N 8192
#define DIMF  128

__device__ float  g_sq[MAX_N];
__device__ double g_acc;
__device__ int    g_is64;   // 1 if triplet buffer is int64, 0 if int32

// Detect dtype: int64 values < 8192 have all-zero high words (odd int32 words).
__global__ void detect_and_init_kernel(const int* __restrict__ trip_raw) {
    if (threadIdx.x == 0) {
        int all0 = 1;
        #pragma unroll 1
        for (int t = 0; t < 64; t++) {
            if (trip_raw[2 * t + 1] != 0) { all0 = 0; break; }
        }
        g_is64 = all0;
        g_acc  = 0.0;
    }
}

__global__ void sq_norm_kernel(const float* __restrict__ feat, int N) {
    int row  = (int)((blockIdx.x * blockDim.x + threadIdx.x) >> 5);
    int lane = threadIdx.x & 31;
    if (row >= N) return;
    float4 v = reinterpret_cast<const float4*>(feat)[row * (DIMF / 4) + lane];
    float s = v.x * v.x + v.y * v.y + v.z * v.z + v.w * v.w;
    #pragma unroll
    for (int o = 16; o; o >>= 1) s += __shfl_xor_sync(0xffffffffu, s, o);
    if (lane == 0) g_sq[row] = s;
}

__device__ __forceinline__ float softplus_f(float z) {
    return fmaxf(z, 0.0f) + log1pf(__expf(-fabsf(z)));   // stable log(1+e^z)
}

__device__ __forceinline__ int load_idx(const void* trip, int is64, int pos, int N) {
    int v = is64 ? (int)reinterpret_cast<const long long*>(trip)[pos]
                 : reinterpret_cast<const int*>(trip)[pos];
    // Harden: never let a bad index crash; wrong answer is caught by rel_err.
    v = v < 0 ? 0 : v;
    return v >= N ? N - 1 : v;
}

__global__ void __launch_bounds__(256) triplet_kernel(
    const float* __restrict__ feat,
    const void* __restrict__ trip,
    int T, int N)
{
    const int lane  = threadIdx.x & 31;
    const int wid   = threadIdx.x >> 5;
    const int gw    = (int)((blockIdx.x * blockDim.x + threadIdx.x) >> 5);
    const int nw    = (int)((gridDim.x * blockDim.x) >> 5);
    const int is64  = g_is64;
    const float4* __restrict__ f4 = reinterpret_cast<const float4*>(feat);

    float sum = 0.0f;

    for (int base = gw * 2; base < T; base += nw * 2) {
        float dij[2], dik[2];
        int   ii[2], jj[2], kk[2];
        bool  act[2];

        #pragma unroll
        for (int u = 0; u < 2; u++) {
            int t  = base + u;
            act[u] = (t < T);
            int tt = act[u] ? t : 0;
            ii[u] = load_idx(trip, is64, 3 * tt + 0, N);
            jj[u] = load_idx(trip, is64, 3 * tt + 1, N);
            kk[u] = load_idx(trip, is64, 3 * tt + 2, N);
            float4 a = f4[ii[u] * (DIMF / 4) + lane];
            float4 b = f4[jj[u] * (DIMF / 4) + lane];
            float4 c = f4[kk[u] * (DIMF / 4) + lane];
            dij[u] = a.x * b.x + a.y * b.y + a.z * b.z + a.w * b.w;
            dik[u] = a.x * c.x + a.y * c.y + a.z * c.z + a.w * c.w;
        }

        #pragma unroll
        for (int o = 16; o; o >>= 1) {
            dij[0] += __shfl_xor_sync(0xffffffffu, dij[0], o);
            dik[0] += __shfl_xor_sync(0xffffffffu, dik[0], o);
            dij[1] += __shfl_xor_sync(0xffffffffu, dij[1], o);
            dik[1] += __shfl_xor_sync(0xffffffffu, dik[1], o);
        }

        #pragma unroll
        for (int u = 0; u < 2; u++) {
            if (act[u]) {
                float si = g_sq[ii[u]];
                float sj = g_sq[jj[u]];
                float sk = g_sq[kk[u]];
                float d1 = fmaxf(si + sj - 2.0f * dij[u], 0.0f);
                float d2 = fmaxf(si + sk - 2.0f * dik[u], 0.0f);
                sum += softplus_f(d1 - d2);   // identical across lanes
            }
        }
    }

    __shared__ float wsum[8];
    if (lane == 0) wsum[wid] = sum;
    __syncthreads();
    if (threadIdx.x == 0) {
        float b = 0.0f;
        #pragma unroll
        for (int w = 0; w < 8; w++) b += wsum[w];
        atomicAdd(&g_acc, (double)b);
    }
}

__global__ void finalize_kernel(float* __restrict__ out, int T) {
    out[0] = (float)(g_acc / (double)T);
}

extern "C" void kernel_launch(void* const* d_in, const int* in_sizes, int n_in,
                              void* d_out, int out_size)
{
    const float* feat = (const float*)d_in[0];
    const void*  trip = d_in[1];
    int N = in_sizes[0] / DIMF;     // 8192
    int T = in_sizes[1] / 3;        // 1,000,000

    detect_and_init_kernel<<<1, 32>>>((const int*)trip);

    int sq_threads = N * 32;
    sq_norm_kernel<<<(sq_threads + 255) / 256, 256>>>(feat, N);

    triplet_kernel<<<1184, 256>>>(feat, trip, T, N);

    finalize_kernel<<<1, 1>>>((float*)d_out, T);
}

// round 3
// speedup vs baseline: 1.6128x; 1.6128x over previous
#include <cuda_runtime.h>
#include <cuda_fp16.h>
#include <cuda_bf16.h>

// TripletLoss on GB300 — R3: fp16 feature cache (halves L2 row traffic).
//   loss = mean_t softplus( d(i,j) - d(i,k) ),  d(a,b)=max(|xa|^2+|xb|^2-2 xa.xb, 0)
// R2 was ~90% of the LTS cap moving 1.54GB of fp32 rows; fp16 rows move 0.77GB.
// Sq-norms stay exact fp32; dots use fp16 inputs + fp32 accumulation
// (est. final rel_err ~1e-5, threshold 1e-3).
// Half-warp (16 lanes x 16B) per triplet row; butterfly is 4 steps.

#define MAX_N 8192
#define DIMF  128

__device__ __half  g_feat_h[MAX_N * DIMF];   // 2 MB fp16 copy
__device__ float   g_sq[MAX_N];
__device__ double  g_acc;
__device__ int     g_is64;

// Detect triplet dtype: int64 values <8192 have all-zero high (odd int32) words.
__global__ void detect_and_init_kernel(const int* __restrict__ trip_raw) {
    if (threadIdx.x == 0) {
        int all0 = 1;
        #pragma unroll 1
        for (int t = 0; t < 64; t++)
            if (trip_raw[2 * t + 1] != 0) { all0 = 0; break; }
        g_is64 = all0;
        g_acc  = 0.0;
    }
}

// fp32 -> fp16 conversion: one thread packs 8 elements (one uint4 of halves).
__global__ void convert_kernel(const float* __restrict__ feat, int total8) {
    int idx = blockIdx.x * blockDim.x + threadIdx.x;
    if (idx >= total8) return;
    const float4* f4 = reinterpret_cast<const float4*>(feat);
    float4 v0 = f4[idx * 2 + 0];
    float4 v1 = f4[idx * 2 + 1];
    __half2 h0 = __floats2half2_rn(v0.x, v0.y);
    __half2 h1 = __floats2half2_rn(v0.z, v0.w);
    __half2 h2 = __floats2half2_rn(v1.x, v1.y);
    __half2 h3 = __floats2half2_rn(v1.z, v1.w);
    uint4 o;
    o.x = *reinterpret_cast<unsigned*>(&h0);
    o.y = *reinterpret_cast<unsigned*>(&h1);
    o.z = *reinterpret_cast<unsigned*>(&h2);
    o.w = *reinterpret_cast<unsigned*>(&h3);
    reinterpret_cast<uint4*>(g_feat_h)[idx] = o;
}

__global__ void sq_norm_kernel(const float* __restrict__ feat, int N) {
    int row  = (int)((blockIdx.x * blockDim.x + threadIdx.x) >> 5);
    int lane = threadIdx.x & 31;
    if (row >= N) return;
    float4 v = reinterpret_cast<const float4*>(feat)[row * (DIMF / 4) + lane];
    float s = v.x * v.x + v.y * v.y + v.z * v.z + v.w * v.w;
    #pragma unroll
    for (int o = 16; o; o >>= 1) s += __shfl_xor_sync(0xffffffffu, s, o);
    if (lane == 0) g_sq[row] = s;
}

__device__ __forceinline__ float softplus_f(float z) {
    return fmaxf(z, 0.0f) + log1pf(__expf(-fabsf(z)));   // stable log(1+e^z)
}

__device__ __forceinline__ int load_idx(const void* trip, int is64, int pos, int N) {
    int v = is64 ? (int)reinterpret_cast<const long long*>(trip)[pos]
                 : reinterpret_cast<const int*>(trip)[pos];
    v = v < 0 ? 0 : v;
    return v >= N ? N - 1 : v;
}

// Accumulate 8 fp16 products (fp32 math) into dij/dik.
__device__ __forceinline__ void dot8(const uint4& A, const uint4& B, const uint4& C,
                                     float& dij, float& dik) {
    const __half2* a = reinterpret_cast<const __half2*>(&A);
    const __half2* b = reinterpret_cast<const __half2*>(&B);
    const __half2* c = reinterpret_cast<const __half2*>(&C);
    #pragma unroll
    for (int q = 0; q < 4; q++) {
        float2 fa = __half22float2(a[q]);
        float2 fb = __half22float2(b[q]);
        float2 fc = __half22float2(c[q]);
        dij = fmaf(fa.x, fb.x, dij); dij = fmaf(fa.y, fb.y, dij);
        dik = fmaf(fa.x, fc.x, dik); dik = fmaf(fa.y, fc.y, dik);
    }
}

__global__ void __launch_bounds__(256) triplet_kernel(
    const void* __restrict__ trip, int T, int N)
{
    const int lane  = threadIdx.x & 31;
    const int wid   = threadIdx.x >> 5;
    const int sub   = lane & 15;        // position within half-warp
    const int hw    = lane >> 4;        // which half-warp (0/1)
    const int gw    = (int)((blockIdx.x * blockDim.x + threadIdx.x) >> 5);
    const int nw    = (int)((gridDim.x * blockDim.x) >> 5);
    const int is64  = g_is64;
    const uint4* __restrict__ fh = reinterpret_cast<const uint4*>(g_feat_h); // 16 uint4/row

    float sum = 0.0f;

    // 4 triplets per warp-iter: 2 unrolled pairs x 2 half-warps.
    for (int base = gw * 4; base < T; base += nw * 4) {
        float dij[2], dik[2];
        int   ii[2], jj[2], kk[2];
        bool  act[2];

        #pragma unroll
        for (int u = 0; u < 2; u++) {
            int t  = base + u * 2 + hw;
            act[u] = (t < T);
            int tt = act[u] ? t : 0;
            ii[u] = load_idx(trip, is64, 3 * tt + 0, N);
            jj[u] = load_idx(trip, is64, 3 * tt + 1, N);
            kk[u] = load_idx(trip, is64, 3 * tt + 2, N);
            uint4 a = fh[ii[u] * 16 + sub];
            uint4 b = fh[jj[u] * 16 + sub];
            uint4 c = fh[kk[u] * 16 + sub];
            dij[u] = 0.0f; dik[u] = 0.0f;
            dot8(a, b, c, dij[u], dik[u]);
        }

        // Butterfly within each 16-lane half: 4 steps x 4 values.
        #pragma unroll
        for (int o = 8; o; o >>= 1) {
            dij[0] += __shfl_xor_sync(0xffffffffu, dij[0], o);
            dik[0] += __shfl_xor_sync(0xffffffffu, dik[0], o);
            dij[1] += __shfl_xor_sync(0xffffffffu, dij[1], o);
            dik[1] += __shfl_xor_sync(0xffffffffu, dik[1], o);
        }

        if (sub == 0) {                 // lanes 0 and 16 own one triplet each
            #pragma unroll
            for (int u = 0; u < 2; u++) {
                if (act[u]) {
                    float si = g_sq[ii[u]];
                    float sj = g_sq[jj[u]];
                    float sk = g_sq[kk[u]];
                    float d1 = fmaxf(si + sj - 2.0f * dij[u], 0.0f);
                    float d2 = fmaxf(si + sk - 2.0f * dik[u], 0.0f);
                    sum += softplus_f(d1 - d2);
                }
            }
        }
    }

    // Warp then block reduction of per-thread sums.
    #pragma unroll
    for (int o = 16; o; o >>= 1) sum += __shfl_xor_sync(0xffffffffu, sum, o);
    __shared__ float wsum[8];
    if (lane == 0) wsum[wid] = sum;
    __syncthreads();
    if (threadIdx.x == 0) {
        float b = 0.0f;
        #pragma unroll
        for (int w = 0; w < 8; w++) b += wsum[w];
        atomicAdd(&g_acc, (double)b);
    }
}

__global__ void finalize_kernel(float* __restrict__ out, int T) {
    out[0] = (float)(g_acc / (double)T);
}

extern "C" void kernel_launch(void* const* d_in, const int* in_sizes, int n_in,
                              void* d_out, int out_size)
{
    const float* feat = (const float*)d_in[0];
    const void*  trip = d_in[1];
    int N = in_sizes[0] / DIMF;     // 8192
    int T = in_sizes[1] / 3;        // 1,000,000

    detect_and_init_kernel<<<1, 32>>>((const int*)trip);

    int total8 = N * DIMF / 8;
    convert_kernel<<<(total8 + 255) / 256, 256>>>(feat, total8);

    sq_norm_kernel<<<(N * 32 + 255) / 256, 256>>>(feat, N);

    triplet_kernel<<<1184, 256>>>(trip, T, N);

    finalize_kernel<<<1, 1>>>((float*)d_out, T);
}

// round 4
// speedup vs baseline: 1.6830x; 1.0435x over previous
#include <cuda_runtime.h>
#include <cuda_fp16.h>
#include <cuda_bf16.h>

// TripletLoss on GB300 — R4: HFMA2 dots + packed half2 butterfly.
// R3 was issue-bound (71.6% issue, fma 41%+alu 34%), not memory bound
// (L2 31.5%, L1 52.3%). This round halves warp-instructions per triplet:
//  - dots accumulate in __half2 via HFMA2 (no per-element converts)
//  - (s_ij,s_ik) packed in one half2 -> 4 SHFL + 4 HADD2 per triplet
//  - index clamp -> single AND mask (N pow2)
// Softplus/epilogue stays fp32; sq-norms exact fp32.

#define MAX_N 8192
#define DIMF  128

__device__ __half  g_feat_h[MAX_N * DIMF];   // 2 MB fp16 copy
__device__ float   g_sq[MAX_N];
__device__ double  g_acc;
__device__ int     g_is64;

__global__ void detect_and_init_kernel(const int* __restrict__ trip_raw) {
    if (threadIdx.x == 0) {
        int all0 = 1;
        #pragma unroll 1
        for (int t = 0; t < 64; t++)
            if (trip_raw[2 * t + 1] != 0) { all0 = 0; break; }
        g_is64 = all0;   // int64 triplets: high words of small values are 0
        g_acc  = 0.0;
    }
}

__global__ void convert_kernel(const float* __restrict__ feat, int total8) {
    int idx = blockIdx.x * blockDim.x + threadIdx.x;
    if (idx >= total8) return;
    const float4* f4 = reinterpret_cast<const float4*>(feat);
    float4 v0 = f4[idx * 2 + 0];
    float4 v1 = f4[idx * 2 + 1];
    __half2 h0 = __floats2half2_rn(v0.x, v0.y);
    __half2 h1 = __floats2half2_rn(v0.z, v0.w);
    __half2 h2 = __floats2half2_rn(v1.x, v1.y);
    __half2 h3 = __floats2half2_rn(v1.z, v1.w);
    uint4 o;
    o.x = *reinterpret_cast<unsigned*>(&h0);
    o.y = *reinterpret_cast<unsigned*>(&h1);
    o.z = *reinterpret_cast<unsigned*>(&h2);
    o.w = *reinterpret_cast<unsigned*>(&h3);
    reinterpret_cast<uint4*>(g_feat_h)[idx] = o;
}

__global__ void sq_norm_kernel(const float* __restrict__ feat, int N) {
    int row  = (int)((blockIdx.x * blockDim.x + threadIdx.x) >> 5);
    int lane = threadIdx.x & 31;
    if (row >= N) return;
    float4 v = reinterpret_cast<const float4*>(feat)[row * (DIMF / 4) + lane];
    float s = v.x * v.x + v.y * v.y + v.z * v.z + v.w * v.w;
    #pragma unroll
    for (int o = 16; o; o >>= 1) s += __shfl_xor_sync(0xffffffffu, s, o);
    if (lane == 0) g_sq[row] = s;
}

__device__ __forceinline__ float softplus_f(float z) {
    return fmaxf(z, 0.0f) + log1pf(__expf(-fabsf(z)));   // stable log(1+e^z)
}

__device__ __forceinline__ int load_idx(const void* trip, int is64, int pos,
                                        int mask, int N) {
    int v = is64 ? (int)reinterpret_cast<const long long*>(trip)[pos]
                 : reinterpret_cast<const int*>(trip)[pos];
    if (mask >= 0) return v & mask;              // N power of 2: 1 LOP
    v = v < 0 ? 0 : v;                           // fallback clamp
    return v >= N ? N - 1 : v;
}

__global__ void __launch_bounds__(256) triplet_kernel(
    const void* __restrict__ trip, int T, int N, int mask)
{
    const int lane  = threadIdx.x & 31;
    const int wid   = threadIdx.x >> 5;
    const int sub   = lane & 15;        // position in half-warp
    const int hw    = lane >> 4;        // half-warp id
    const int gw    = (int)((blockIdx.x * blockDim.x + threadIdx.x) >> 5);
    const int nw    = (int)((gridDim.x * blockDim.x) >> 5);
    const int is64  = g_is64;
    const uint4* __restrict__ fh = reinterpret_cast<const uint4*>(g_feat_h);

    float sum = 0.0f;

    // 4 triplets per warp-iter: 2 unrolled x 2 half-warps.
    for (int base = gw * 4; base < T; base += nw * 4) {
        __half2 pk[2];                  // packed (s_ij, s_ik) per unroll slot
        int   ii[2], jj[2], kk[2];
        bool  act[2];

        #pragma unroll
        for (int u = 0; u < 2; u++) {
            int t  = base + u * 2 + hw;
            act[u] = (t < T);
            int tt = act[u] ? t : 0;
            ii[u] = load_idx(trip, is64, 3 * tt + 0, mask, N);
            jj[u] = load_idx(trip, is64, 3 * tt + 1, mask, N);
            kk[u] = load_idx(trip, is64, 3 * tt + 2, mask, N);
            uint4 A = fh[ii[u] * 16 + sub];
            uint4 B = fh[jj[u] * 16 + sub];
            uint4 C = fh[kk[u] * 16 + sub];
            const __half2* a = reinterpret_cast<const __half2*>(&A);
            const __half2* b = reinterpret_cast<const __half2*>(&B);
            const __half2* c = reinterpret_cast<const __half2*>(&C);
            __half2 aij = __float2half2_rn(0.0f);
            __half2 aik = __float2half2_rn(0.0f);
            #pragma unroll
            for (int q = 0; q < 4; q++) {
                aij = __hfma2(a[q], b[q], aij);
                aik = __hfma2(a[q], c[q], aik);
            }
            // fold halves: ( sum(aij), sum(aik) ) in one half2
            pk[u] = __hadd2(__lows2half2(aij, aik), __highs2half2(aij, aik));
        }

        // Packed butterfly over 16-lane halves: 4 steps x 2 slots.
        #pragma unroll
        for (int o = 8; o; o >>= 1) {
            unsigned p0 = *reinterpret_cast<unsigned*>(&pk[0]);
            unsigned p1 = *reinterpret_cast<unsigned*>(&pk[1]);
            unsigned q0 = __shfl_xor_sync(0xffffffffu, p0, o);
            unsigned q1 = __shfl_xor_sync(0xffffffffu, p1, o);
            pk[0] = __hadd2(pk[0], *reinterpret_cast<__half2*>(&q0));
            pk[1] = __hadd2(pk[1], *reinterpret_cast<__half2*>(&q1));
        }

        if (sub == 0) {                 // lanes 0 / 16 own one triplet each
            #pragma unroll
            for (int u = 0; u < 2; u++) {
                if (act[u]) {
                    float dij = __low2float(pk[u]);
                    float dik = __high2float(pk[u]);
                    float si = g_sq[ii[u]];
                    float sj = g_sq[jj[u]];
                    float sk = g_sq[kk[u]];
                    float d1 = fmaxf(si + sj - 2.0f * dij, 0.0f);
                    float d2 = fmaxf(si + sk - 2.0f * dik, 0.0f);
                    sum += softplus_f(d1 - d2);
                }
            }
        }
    }

    #pragma unroll
    for (int o = 16; o; o >>= 1) sum += __shfl_xor_sync(0xffffffffu, sum, o);
    __shared__ float wsum[8];
    if (lane == 0) wsum[wid] = sum;
    __syncthreads();
    if (threadIdx.x == 0) {
        float b = 0.0f;
        #pragma unroll
        for (int w = 0; w < 8; w++) b += wsum[w];
        atomicAdd(&g_acc, (double)b);
    }
}

__global__ void finalize_kernel(float* __restrict__ out, int T) {
    out[0] = (float)(g_acc / (double)T);
}

extern "C" void kernel_launch(void* const* d_in, const int* in_sizes, int n_in,
                              void* d_out, int out_size)
{
    const float* feat = (const float*)d_in[0];
    const void*  trip = d_in[1];
    int N = in_sizes[0] / DIMF;     // 8192
    int T = in_sizes[1] / 3;        // 1,000,000
    int mask = ((N & (N - 1)) == 0) ? (N - 1) : -1;

    detect_and_init_kernel<<<1, 32>>>((const int*)trip);

    int total8 = N * DIMF / 8;
    convert_kernel<<<(total8 + 255) / 256, 256>>>(feat, total8);

    sq_norm_kernel<<<(N * 32 + 255) / 256, 256>>>(feat, N);

    triplet_kernel<<<1184, 256>>>(trip, T, N, mask);

    finalize_kernel<<<1, 1>>>((float*)d_out, T);
}

// round 5
// speedup vs baseline: 2.6973x; 1.6027x over previous
#include <cuda_runtime.h>
#include <cuda_fp16.h>
#include <cuda_bf16.h>

// TripletLoss on GB300 — R5: int8+DP4A, 8 lanes/triplet, 4-wide epilogue.
//   loss = mean_t softplus( d(i,j) - d(i,k) ),  d=max(|xi|^2+|xj|^2-2 xi.xj, 0)
// R4 was issue-bound on per-triplet overhead (alu 43.6%, issue 65.6%).
// This round: int8 rows (128B -> 8-lane groups), exact int32 DP4A dots,
// 3-step butterfly, 4 triplets/warp in parallel (epilogue 4-wide), unroll x2.
// Norms stay exact fp32; only dots quantized (z err sigma ~0.4 vs spread ~45).

#define MAX_N 8192
#define DIMF  128

__device__ signed char g_feat_q[MAX_N * DIMF];   // 1 MB int8 copy
__device__ float       g_sq[MAX_N];
__device__ float       g_c2;                     // -2 * scale^2
__device__ unsigned    g_absmax_bits;
__device__ double      g_acc;
__device__ int         g_is64;

__global__ void detect_and_init_kernel(const int* __restrict__ trip_raw) {
    if (threadIdx.x == 0) {
        int all0 = 1;
        #pragma unroll 1
        for (int t = 0; t < 64; t++)
            if (trip_raw[2 * t + 1] != 0) { all0 = 0; break; }
        g_is64 = all0;          // int64 triplets: high words of small values = 0
        g_acc = 0.0;
        g_absmax_bits = 0u;
    }
}

__global__ void absmax_kernel(const float* __restrict__ feat, int total4) {
    int i = blockIdx.x * blockDim.x + threadIdx.x;
    const float4* f4 = reinterpret_cast<const float4*>(feat);
    float v = 0.0f;
    for (; i < total4; i += gridDim.x * blockDim.x) {
        float4 x = f4[i];
        v = fmaxf(v, fmaxf(fmaxf(fabsf(x.x), fabsf(x.y)),
                           fmaxf(fabsf(x.z), fabsf(x.w))));
    }
    #pragma unroll
    for (int o = 16; o; o >>= 1)
        v = fmaxf(v, __shfl_xor_sync(0xffffffffu, v, o));
    if ((threadIdx.x & 31) == 0)
        atomicMax(&g_absmax_bits, __float_as_uint(v));   // positive floats: bit order = value order
}

__global__ void quant_kernel(const float* __restrict__ feat, int total4) {
    int idx = blockIdx.x * blockDim.x + threadIdx.x;
    if (idx >= total4) return;
    float absmax = __uint_as_float(g_absmax_bits);
    float s = 127.0f / absmax;
    if (idx == 0) {
        float sc = absmax / 127.0f;
        g_c2 = -2.0f * sc * sc;
    }
    float4 v = reinterpret_cast<const float4*>(feat)[idx];
    int q0 = max(-127, min(127, __float2int_rn(v.x * s)));
    int q1 = max(-127, min(127, __float2int_rn(v.y * s)));
    int q2 = max(-127, min(127, __float2int_rn(v.z * s)));
    int q3 = max(-127, min(127, __float2int_rn(v.w * s)));
    unsigned packed = (unsigned)(q0 & 0xFF) | ((unsigned)(q1 & 0xFF) << 8) |
                      ((unsigned)(q2 & 0xFF) << 16) | ((unsigned)(q3 & 0xFF) << 24);
    reinterpret_cast<unsigned*>(g_feat_q)[idx] = packed;
}

__global__ void sq_norm_kernel(const float* __restrict__ feat, int N) {
    int row  = (int)((blockIdx.x * blockDim.x + threadIdx.x) >> 5);
    int lane = threadIdx.x & 31;
    if (row >= N) return;
    float4 v = reinterpret_cast<const float4*>(feat)[row * (DIMF / 4) + lane];
    float s = v.x * v.x + v.y * v.y + v.z * v.z + v.w * v.w;
    #pragma unroll
    for (int o = 16; o; o >>= 1) s += __shfl_xor_sync(0xffffffffu, s, o);
    if (lane == 0) g_sq[row] = s;
}

__device__ __forceinline__ float softplus_f(float z) {
    return fmaxf(z, 0.0f) + log1pf(__expf(-fabsf(z)));   // stable log(1+e^z)
}

__device__ __forceinline__ int load_idx(const void* trip, int is64, int pos,
                                        int mask, int N) {
    int v = is64 ? (int)reinterpret_cast<const long long*>(trip)[pos]
                 : reinterpret_cast<const int*>(trip)[pos];
    if (mask >= 0) return v & mask;              // N pow2: single LOP
    v = v < 0 ? 0 : v;
    return v >= N ? N - 1 : v;
}

__global__ void __launch_bounds__(256) triplet_kernel(
    const void* __restrict__ trip, int T, int N, int mask)
{
    const int lane = threadIdx.x & 31;
    const int wid  = threadIdx.x >> 5;
    const int sub  = lane & 7;          // position in 8-lane group
    const int grp  = lane >> 3;         // group 0..3
    const int gw   = (int)((blockIdx.x * blockDim.x + threadIdx.x) >> 5);
    const int nw   = (int)((gridDim.x * blockDim.x) >> 5);
    const int is64 = g_is64;
    const float c2 = g_c2;
    const uint4* __restrict__ fq = reinterpret_cast<const uint4*>(g_feat_q); // 8 uint4/row

    float sum = 0.0f;

    // 8 triplets per warp-iter: 2 unrolled x 4 groups.
    for (int base = gw * 8; base < T; base += nw * 8) {
        int  Iij[2], Iik[2];
        int  ii[2], jj[2], kk[2];
        bool act[2];

        #pragma unroll
        for (int u = 0; u < 2; u++) {
            int t  = base + u * 4 + grp;
            act[u] = (t < T);
            int tt = act[u] ? t : 0;
            ii[u] = load_idx(trip, is64, 3 * tt + 0, mask, N);
            jj[u] = load_idx(trip, is64, 3 * tt + 1, mask, N);
            kk[u] = load_idx(trip, is64, 3 * tt + 2, mask, N);
            uint4 A = fq[ii[u] * 8 + sub];
            uint4 B = fq[jj[u] * 8 + sub];
            uint4 C = fq[kk[u] * 8 + sub];
            int dij = 0, dik = 0;
            dij = __dp4a((int)A.x, (int)B.x, dij);
            dik = __dp4a((int)A.x, (int)C.x, dik);
            dij = __dp4a((int)A.y, (int)B.y, dij);
            dik = __dp4a((int)A.y, (int)C.y, dik);
            dij = __dp4a((int)A.z, (int)B.z, dij);
            dik = __dp4a((int)A.z, (int)C.z, dik);
            dij = __dp4a((int)A.w, (int)B.w, dij);
            dik = __dp4a((int)A.w, (int)C.w, dik);
            Iij[u] = dij; Iik[u] = dik;
        }

        // Butterfly within 8-lane groups: 3 steps x 4 values.
        #pragma unroll
        for (int o = 4; o; o >>= 1) {
            Iij[0] += __shfl_xor_sync(0xffffffffu, Iij[0], o);
            Iik[0] += __shfl_xor_sync(0xffffffffu, Iik[0], o);
            Iij[1] += __shfl_xor_sync(0xffffffffu, Iij[1], o);
            Iik[1] += __shfl_xor_sync(0xffffffffu, Iik[1], o);
        }

        if (sub == 0) {                 // lanes 0,8,16,24 work in parallel
            #pragma unroll
            for (int u = 0; u < 2; u++) {
                if (act[u]) {
                    float si = g_sq[ii[u]];
                    float sj = g_sq[jj[u]];
                    float sk = g_sq[kk[u]];
                    float d1 = fmaxf(fmaf(c2, (float)Iij[u], si + sj), 0.0f);
                    float d2 = fmaxf(fmaf(c2, (float)Iik[u], si + sk), 0.0f);
                    sum += softplus_f(d1 - d2);
                }
            }
        }
    }

    #pragma unroll
    for (int o = 16; o; o >>= 1) sum += __shfl_xor_sync(0xffffffffu, sum, o);
    __shared__ float wsum[8];
    if (lane == 0) wsum[wid] = sum;
    __syncthreads();
    if (threadIdx.x == 0) {
        float b = 0.0f;
        #pragma unroll
        for (int w = 0; w < 8; w++) b += wsum[w];
        atomicAdd(&g_acc, (double)b);
    }
}

__global__ void finalize_kernel(float* __restrict__ out, int T) {
    out[0] = (float)(g_acc / (double)T);
}

extern "C" void kernel_launch(void* const* d_in, const int* in_sizes, int n_in,
                              void* d_out, int out_size)
{
    const float* feat = (const float*)d_in[0];
    const void*  trip = d_in[1];
    int N = in_sizes[0] / DIMF;     // 8192
    int T = in_sizes[1] / 3;        // 1,000,000
    int mask = ((N & (N - 1)) == 0) ? (N - 1) : -1;
    int total4 = N * DIMF / 4;

    detect_and_init_kernel<<<1, 32>>>((const int*)trip);
    absmax_kernel<<<592, 256>>>(feat, total4);
    quant_kernel<<<(total4 + 255) / 256, 256>>>(feat, total4);
    sq_norm_kernel<<<(N * 32 + 255) / 256, 256>>>(feat, N);
    triplet_kernel<<<1184, 256>>>(trip, T, N, mask);
    finalize_kernel<<<1, 1>>>((float*)d_out, T);
}

// round 6
// speedup vs baseline: 3.3066x; 1.2259x over previous
#include <cuda_runtime.h>
#include <cuda_fp16.h>
#include <cuda_bf16.h>

// TripletLoss on GB300 — R6: fused pre-pass, fast-math softplus, unroll x4
// with occupancy-sized single-wave grid.
//   loss = mean_t softplus( d(i,j) - d(i,k) ),  d=max(|xi|^2+|xj|^2-2 xi.xj, 0)
// R5 analysis: main kernel ~45us vs ~10us issue floor -> latency-bound on
// random 128B row gathers; plus ~12us of preprocessing launches.
//  - absmax fused into sq_norm pass (one less 4MB sweep + launch)
//  - softplus via __logf/__expf (log1pf was a slow software routine)
//  - 16 triplets/warp-iter (4 groups x 4 unroll) for 2x load MLP
//  - grid = occupancy blocks x SMs (exactly one wave, no tail imbalance)

#define MAX_N 8192
#define DIMF  128

__device__ signed char g_feat_q[MAX_N * DIMF];   // 1 MB int8 copy
__device__ float       g_sq[MAX_N];
__device__ float       g_c2;                     // -2 * scale^2
__device__ unsigned    g_absmax_bits;
__device__ double      g_acc;
__device__ int         g_is64;

__global__ void detect_and_init_kernel(const int* __restrict__ trip_raw) {
    if (threadIdx.x == 0) {
        int all0 = 1;
        #pragma unroll 1
        for (int t = 0; t < 64; t++)
            if (trip_raw[2 * t + 1] != 0) { all0 = 0; break; }
        g_is64 = all0;          // int64 triplets: high words of small values = 0
        g_acc = 0.0;
        g_absmax_bits = 0u;
    }
}

// Fused: per-row squared norm (exact fp32) + global absmax (block-reduced).
__global__ void norm_absmax_kernel(const float* __restrict__ feat, int N) {
    int row  = (int)((blockIdx.x * blockDim.x + threadIdx.x) >> 5);
    int lane = threadIdx.x & 31;
    int wid  = threadIdx.x >> 5;
    float s = 0.0f, m = 0.0f;
    if (row < N) {
        float4 v = reinterpret_cast<const float4*>(feat)[row * (DIMF / 4) + lane];
        s = v.x * v.x + v.y * v.y + v.z * v.z + v.w * v.w;
        m = fmaxf(fmaxf(fabsf(v.x), fabsf(v.y)), fmaxf(fabsf(v.z), fabsf(v.w)));
    }
    #pragma unroll
    for (int o = 16; o; o >>= 1) {
        s += __shfl_xor_sync(0xffffffffu, s, o);
        m  = fmaxf(m, __shfl_xor_sync(0xffffffffu, m, o));
    }
    if (lane == 0 && row < N) g_sq[row] = s;
    __shared__ float wmax[8];
    if (lane == 0) wmax[wid] = m;
    __syncthreads();
    if (threadIdx.x == 0) {
        float bm = 0.0f;
        #pragma unroll
        for (int w = 0; w < 8; w++) bm = fmaxf(bm, wmax[w]);
        atomicMax(&g_absmax_bits, __float_as_uint(bm));  // positive floats: bit order = value order
    }
}

__global__ void quant_kernel(const float* __restrict__ feat, int total4) {
    int idx = blockIdx.x * blockDim.x + threadIdx.x;
    if (idx >= total4) return;
    float absmax = __uint_as_float(g_absmax_bits);
    float s = 127.0f / absmax;
    if (idx == 0) {
        float sc = absmax / 127.0f;
        g_c2 = -2.0f * sc * sc;
    }
    float4 v = reinterpret_cast<const float4*>(feat)[idx];
    int q0 = max(-127, min(127, __float2int_rn(v.x * s)));
    int q1 = max(-127, min(127, __float2int_rn(v.y * s)));
    int q2 = max(-127, min(127, __float2int_rn(v.z * s)));
    int q3 = max(-127, min(127, __float2int_rn(v.w * s)));
    unsigned packed = (unsigned)(q0 & 0xFF) | ((unsigned)(q1 & 0xFF) << 8) |
                      ((unsigned)(q2 & 0xFF) << 16) | ((unsigned)(q3 & 0xFF) << 24);
    reinterpret_cast<unsigned*>(g_feat_q)[idx] = packed;
}

__device__ __forceinline__ float softplus_fast(float z) {
    // log(1+e^z) = max(z,0) + log(1 + e^-|z|); arg of log in (1,2] -> fast mufu ok
    return fmaxf(z, 0.0f) + __logf(1.0f + __expf(-fabsf(z)));
}

__device__ __forceinline__ int load_idx(const void* trip, int is64, int pos,
                                        int mask, int N) {
    int v = is64 ? (int)reinterpret_cast<const long long*>(trip)[pos]
                 : reinterpret_cast<const int*>(trip)[pos];
    if (mask >= 0) return v & mask;              // N pow2: single LOP
    v = v < 0 ? 0 : v;
    return v >= N ? N - 1 : v;
}

#define UNROLL_T 4

__global__ void __launch_bounds__(256) triplet_kernel(
    const void* __restrict__ trip, int T, int N, int mask)
{
    const int lane = threadIdx.x & 31;
    const int wid  = threadIdx.x >> 5;
    const int sub  = lane & 7;          // position in 8-lane group
    const int grp  = lane >> 3;         // group 0..3
    const int gw   = (int)((blockIdx.x * blockDim.x + threadIdx.x) >> 5);
    const int nw   = (int)((gridDim.x * blockDim.x) >> 5);
    const int is64 = g_is64;
    const float c2 = g_c2;
    const uint4* __restrict__ fq = reinterpret_cast<const uint4*>(g_feat_q); // 8 uint4/row

    float sum = 0.0f;

    // 16 triplets per warp-iter: 4 unrolled x 4 groups of 8 lanes.
    for (int base = gw * (4 * UNROLL_T); base < T; base += nw * (4 * UNROLL_T)) {
        int   Iij[UNROLL_T], Iik[UNROLL_T];
        float n1[UNROLL_T], n2[UNROLL_T];

        #pragma unroll
        for (int u = 0; u < UNROLL_T; u++) {
            int t  = base + u * 4 + grp;
            int tt = t < T ? t : 0;
            int ii = load_idx(trip, is64, 3 * tt + 0, mask, N);
            int jj = load_idx(trip, is64, 3 * tt + 1, mask, N);
            int kk = load_idx(trip, is64, 3 * tt + 2, mask, N);
            uint4 A = fq[ii * 8 + sub];
            uint4 B = fq[jj * 8 + sub];
            uint4 C = fq[kk * 8 + sub];
            int dij = 0, dik = 0;
            dij = __dp4a((int)A.x, (int)B.x, dij);
            dik = __dp4a((int)A.x, (int)C.x, dik);
            dij = __dp4a((int)A.y, (int)B.y, dij);
            dik = __dp4a((int)A.y, (int)C.y, dik);
            dij = __dp4a((int)A.z, (int)B.z, dij);
            dik = __dp4a((int)A.z, (int)C.z, dik);
            dij = __dp4a((int)A.w, (int)B.w, dij);
            dik = __dp4a((int)A.w, (int)C.w, dik);
            Iij[u] = dij; Iik[u] = dik;
            n1[u] = 0.0f; n2[u] = 0.0f;
            if (sub == 0) {             // lanes 0,8,16,24 gather norms now
                float si = g_sq[ii];
                n1[u] = si + g_sq[jj];
                n2[u] = si + g_sq[kk];
            }
        }

        // Butterfly within 8-lane groups: 3 steps x 2*UNROLL_T values.
        #pragma unroll
        for (int o = 4; o; o >>= 1) {
            #pragma unroll
            for (int u = 0; u < UNROLL_T; u++) {
                Iij[u] += __shfl_xor_sync(0xffffffffu, Iij[u], o);
                Iik[u] += __shfl_xor_sync(0xffffffffu, Iik[u], o);
            }
        }

        if (sub == 0) {                 // 4 lanes in parallel
            #pragma unroll
            for (int u = 0; u < UNROLL_T; u++) {
                if (base + u * 4 + grp < T) {
                    float d1 = fmaxf(fmaf(c2, (float)Iij[u], n1[u]), 0.0f);
                    float d2 = fmaxf(fmaf(c2, (float)Iik[u], n2[u]), 0.0f);
                    sum += softplus_fast(d1 - d2);
                }
            }
        }
    }

    #pragma unroll
    for (int o = 16; o; o >>= 1) sum += __shfl_xor_sync(0xffffffffu, sum, o);
    __shared__ float wsum[8];
    if (lane == 0) wsum[wid] = sum;
    __syncthreads();
    if (threadIdx.x == 0) {
        float b = 0.0f;
        #pragma unroll
        for (int w = 0; w < 8; w++) b += wsum[w];
        atomicAdd(&g_acc, (double)b);
    }
}

__global__ void finalize_kernel(float* __restrict__ out, int T) {
    out[0] = (float)(g_acc / (double)T);
}

extern "C" void kernel_launch(void* const* d_in, const int* in_sizes, int n_in,
                              void* d_out, int out_size)
{
    const float* feat = (const float*)d_in[0];
    const void*  trip = d_in[1];
    int N = in_sizes[0] / DIMF;     // 8192
    int T = in_sizes[1] / 3;        // 1,000,000
    int mask = ((N & (N - 1)) == 0) ? (N - 1) : -1;
    int total4 = N * DIMF / 4;

    // Single-wave grid: resident blocks per SM x SM count (pure queries,
    // capture-safe, deterministic).
    int dev = 0, nsm = 148, bpm = 8;
    cudaGetDevice(&dev);
    cudaDeviceGetAttribute(&nsm, cudaDevAttrMultiProcessorCount, dev);
    cudaOccupancyMaxActiveBlocksPerMultiprocessor(&bpm, triplet_kernel, 256, 0);
    if (bpm < 1) bpm = 1;
    int grid = nsm * bpm;

    detect_and_init_kernel<<<1, 32>>>((const int*)trip);
    norm_absmax_kernel<<<(N * 32 + 255) / 256, 256>>>(feat, N);
    quant_kernel<<<(total4 + 255) / 256, 256>>>(feat, total4);
    triplet_kernel<<<grid, 256>>>(trip, T, N, mask);
    finalize_kernel<<<1, 1>>>((float*)d_out, T);
}

// round 7
// speedup vs baseline: 3.7637x; 1.1382x over previous
#include <cuda_runtime.h>
#include <cuda_fp16.h>
#include <cuda_bf16.h>

// TripletLoss on GB300 — R7: 1-MUFU softplus, 4-lane groups, MLP'd pre-pass.
//   loss = mean_t softplus( d(i,j) - d(i,k) ),  d=max(|xi|^2+|xj|^2-2 xi.xj, 0)
// R6 analysis: hidden MUFU floor ~15us (exp+log per triplet), issue 59%,
// L1 61%. This round:
//  - softplus: r=expf(-|z|); |z|>2.77 (95%) -> cubic log1p(r) (3 FFMA),
//    rare slow path keeps __logf. ~1.05 MUFU/triplet.
//  - 4-lane groups: 8 triplets/warp parallel, 2-step butterfly, 8-wide epilogue.
//  - pre-kernels get MLP>=2; dtype-detect warp-parallel.

#define MAX_N 8192
#define DIMF  128

__device__ signed char g_feat_q[MAX_N * DIMF];   // 1 MB int8 copy
__device__ float       g_sq[MAX_N];
__device__ float       g_c2;                     // -2 * scale^2
__device__ unsigned    g_absmax_bits;
__device__ double      g_acc;
__device__ int         g_is64;

__global__ void detect_and_init_kernel(const int* __restrict__ trip_raw) {
    int lane = threadIdx.x;
    int nz = 0;
    #pragma unroll
    for (int t = lane; t < 64; t += 32) nz |= trip_raw[2 * t + 1];
    unsigned any = __ballot_sync(0xffffffffu, nz != 0);
    if (lane == 0) {
        g_is64 = (any == 0);    // int64 triplets: high words of small values = 0
        g_acc = 0.0;
        g_absmax_bits = 0u;
    }
}

// Per-row squared norm (exact fp32) + global absmax. 2 rows per warp (MLP=2).
__global__ void norm_absmax_kernel(const float* __restrict__ feat, int N) {
    int w    = (int)((blockIdx.x * blockDim.x + threadIdx.x) >> 5);
    int lane = threadIdx.x & 31;
    int wid  = threadIdx.x >> 5;
    int r0 = w * 2, r1 = w * 2 + 1;
    float s0 = 0.0f, s1 = 0.0f, m = 0.0f;
    const float4* f4 = reinterpret_cast<const float4*>(feat);
    if (r0 < N) {
        float4 a = f4[r0 * (DIMF / 4) + lane];
        float4 b = f4[(r1 < N ? r1 : r0) * (DIMF / 4) + lane];
        s0 = a.x * a.x + a.y * a.y + a.z * a.z + a.w * a.w;
        s1 = b.x * b.x + b.y * b.y + b.z * b.z + b.w * b.w;
        m  = fmaxf(fmaxf(fabsf(a.x), fabsf(a.y)), fmaxf(fabsf(a.z), fabsf(a.w)));
        m  = fmaxf(m, fmaxf(fmaxf(fabsf(b.x), fabsf(b.y)), fmaxf(fabsf(b.z), fabsf(b.w))));
    }
    #pragma unroll
    for (int o = 16; o; o >>= 1) {
        s0 += __shfl_xor_sync(0xffffffffu, s0, o);
        s1 += __shfl_xor_sync(0xffffffffu, s1, o);
        m   = fmaxf(m, __shfl_xor_sync(0xffffffffu, m, o));
    }
    if (lane == 0 && r0 < N) {
        g_sq[r0] = s0;
        if (r1 < N) g_sq[r1] = s1;
    }
    __shared__ float wmax[8];
    if (lane == 0) wmax[wid] = m;
    __syncthreads();
    if (threadIdx.x == 0) {
        float bm = 0.0f;
        #pragma unroll
        for (int w2 = 0; w2 < 8; w2++) bm = fmaxf(bm, wmax[w2]);
        atomicMax(&g_absmax_bits, __float_as_uint(bm));  // positive floats: bit order = value order
    }
}

// int8 quantization, 2 float4 per thread (MLP=2).
__global__ void quant_kernel(const float* __restrict__ feat, int total4) {
    int half = total4 >> 1;
    int i0 = blockIdx.x * blockDim.x + threadIdx.x;
    if (i0 >= half) return;
    float absmax = __uint_as_float(g_absmax_bits);
    float s = __fdividef(127.0f, absmax);
    if (i0 == 0) {
        float sc = absmax / 127.0f;
        g_c2 = -2.0f * sc * sc;
    }
    const float4* f4 = reinterpret_cast<const float4*>(feat);
    unsigned* out = reinterpret_cast<unsigned*>(g_feat_q);
    #pragma unroll
    for (int h = 0; h < 2; h++) {
        int idx = i0 + h * half;
        float4 v = f4[idx];
        int q0 = max(-127, min(127, __float2int_rn(v.x * s)));
        int q1 = max(-127, min(127, __float2int_rn(v.y * s)));
        int q2 = max(-127, min(127, __float2int_rn(v.z * s)));
        int q3 = max(-127, min(127, __float2int_rn(v.w * s)));
        out[idx] = (unsigned)(q0 & 0xFF) | ((unsigned)(q1 & 0xFF) << 8) |
                   ((unsigned)(q2 & 0xFF) << 16) | ((unsigned)(q3 & 0xFF) << 24);
    }
}

// softplus with ~1 MUFU: r = e^-|z| in (0,1];
// r<1/16 (95% of triplets): log1p(r) ~= r - r^2/2 + r^3/3 (err < 4e-6).
__device__ __forceinline__ float softplus_1mufu(float z) {
    float r = __expf(-fabsf(z));
    float l;
    if (r < 0.0625f)
        l = r * fmaf(r, fmaf(r, 0.33333333f, -0.5f), 1.0f);
    else
        l = __logf(1.0f + r);
    return fmaxf(z, 0.0f) + l;
}

__device__ __forceinline__ int load_idx(const void* trip, int is64, int pos,
                                        int mask, int N) {
    int v = is64 ? (int)reinterpret_cast<const long long*>(trip)[pos]
                 : reinterpret_cast<const int*>(trip)[pos];
    if (mask >= 0) return v & mask;              // N pow2: single LOP
    v = v < 0 ? 0 : v;
    return v >= N ? N - 1 : v;
}

#define UNROLL_T 2

__global__ void __launch_bounds__(256) triplet_kernel(
    const void* __restrict__ trip, int T, int N, int mask)
{
    const int lane = threadIdx.x & 31;
    const int wid  = threadIdx.x >> 5;
    const int sub  = lane & 3;          // position in 4-lane group
    const int grp  = lane >> 2;         // group 0..7
    const int gw   = (int)((blockIdx.x * blockDim.x + threadIdx.x) >> 5);
    const int nw   = (int)((gridDim.x * blockDim.x) >> 5);
    const int is64 = g_is64;
    const float c2 = g_c2;
    const uint4* __restrict__ fq = reinterpret_cast<const uint4*>(g_feat_q); // 8 uint4/row

    float sum = 0.0f;

    // 16 triplets per warp-iter: 2 unrolled x 8 groups of 4 lanes.
    for (int base = gw * (8 * UNROLL_T); base < T; base += nw * (8 * UNROLL_T)) {
        int   Iij[UNROLL_T], Iik[UNROLL_T];
        float n1[UNROLL_T], n2[UNROLL_T];

        #pragma unroll
        for (int u = 0; u < UNROLL_T; u++) {
            int t  = base + u * 8 + grp;
            int tt = t < T ? t : 0;
            int ii = load_idx(trip, is64, 3 * tt + 0, mask, N);
            int jj = load_idx(trip, is64, 3 * tt + 1, mask, N);
            int kk = load_idx(trip, is64, 3 * tt + 2, mask, N);
            uint4 A0 = fq[ii * 8 + sub], A1 = fq[ii * 8 + sub + 4];
            uint4 B0 = fq[jj * 8 + sub], B1 = fq[jj * 8 + sub + 4];
            uint4 C0 = fq[kk * 8 + sub], C1 = fq[kk * 8 + sub + 4];
            int dij = 0, dik = 0;
            dij = __dp4a((int)A0.x, (int)B0.x, dij);
            dik = __dp4a((int)A0.x, (int)C0.x, dik);
            dij = __dp4a((int)A0.y, (int)B0.y, dij);
            dik = __dp4a((int)A0.y, (int)C0.y, dik);
            dij = __dp4a((int)A0.z, (int)B0.z, dij);
            dik = __dp4a((int)A0.z, (int)C0.z, dik);
            dij = __dp4a((int)A0.w, (int)B0.w, dij);
            dik = __dp4a((int)A0.w, (int)C0.w, dik);
            dij = __dp4a((int)A1.x, (int)B1.x, dij);
            dik = __dp4a((int)A1.x, (int)C1.x, dik);
            dij = __dp4a((int)A1.y, (int)B1.y, dij);
            dik = __dp4a((int)A1.y, (int)C1.y, dik);
            dij = __dp4a((int)A1.z, (int)B1.z, dij);
            dik = __dp4a((int)A1.z, (int)C1.z, dik);
            dij = __dp4a((int)A1.w, (int)B1.w, dij);
            dik = __dp4a((int)A1.w, (int)C1.w, dik);
            Iij[u] = dij; Iik[u] = dik;
            n1[u] = 0.0f; n2[u] = 0.0f;
            if (sub == 0) {             // lanes 0,4,...,28 gather norms
                float si = g_sq[ii];
                n1[u] = si + g_sq[jj];
                n2[u] = si + g_sq[kk];
            }
        }

        // Butterfly within 4-lane groups: 2 steps.
        #pragma unroll
        for (int o = 2; o; o >>= 1) {
            #pragma unroll
            for (int u = 0; u < UNROLL_T; u++) {
                Iij[u] += __shfl_xor_sync(0xffffffffu, Iij[u], o);
                Iik[u] += __shfl_xor_sync(0xffffffffu, Iik[u], o);
            }
        }

        if (sub == 0) {                 // 8 lanes in parallel
            #pragma unroll
            for (int u = 0; u < UNROLL_T; u++) {
                if (base + u * 8 + grp < T) {
                    float d1 = fmaxf(fmaf(c2, (float)Iij[u], n1[u]), 0.0f);
                    float d2 = fmaxf(fmaf(c2, (float)Iik[u], n2[u]), 0.0f);
                    sum += softplus_1mufu(d1 - d2);
                }
            }
        }
    }

    #pragma unroll
    for (int o = 16; o; o >>= 1) sum += __shfl_xor_sync(0xffffffffu, sum, o);
    __shared__ float wsum[8];
    if (lane == 0) wsum[wid] = sum;
    __syncthreads();
    if (threadIdx.x == 0) {
        float b = 0.0f;
        #pragma unroll
        for (int w = 0; w < 8; w++) b += wsum[w];
        atomicAdd(&g_acc, (double)b);
    }
}

__global__ void finalize_kernel(float* __restrict__ out, int T) {
    out[0] = (float)(g_acc / (double)T);
}

extern "C" void kernel_launch(void* const* d_in, const int* in_sizes, int n_in,
                              void* d_out, int out_size)
{
    const float* feat = (const float*)d_in[0];
    const void*  trip = d_in[1];
    int N = in_sizes[0] / DIMF;     // 8192
    int T = in_sizes[1] / 3;        // 1,000,000
    int mask = ((N & (N - 1)) == 0) ? (N - 1) : -1;
    int total4 = N * DIMF / 4;

    // Single-wave grid from occupancy (pure queries; capture-safe).
    int dev = 0, nsm = 148, bpm = 8;
    cudaGetDevice(&dev);
    cudaDeviceGetAttribute(&nsm, cudaDevAttrMultiProcessorCount, dev);
    cudaOccupancyMaxActiveBlocksPerMultiprocessor(&bpm, triplet_kernel, 256, 0);
    if (bpm < 1) bpm = 1;
    int grid = nsm * bpm;

    detect_and_init_kernel<<<1, 32>>>((const int*)trip);
    norm_absmax_kernel<<<(N / 2 * 32 + 255) / 256, 256>>>(feat, N);
    quant_kernel<<<((total4 / 2) + 255) / 256, 256>>>(feat, total4);
    triplet_kernel<<<grid, 256>>>(trip, T, N, mask);
    finalize_kernel<<<1, 1>>>((float*)d_out, T);
}